// round 8
// baseline (speedup 1.0000x reference)
#include <cuda_runtime.h>
#include <cuda_fp16.h>
#include <cstdint>

#define HN 16
#define DD 64
#define BQ 64
#define BK 64
#define NT 128
#define KCAP 4          // k-tiles per split CTA
#define NSGRID 12       // max splits (covers span up to 48 tiles)
#define MAXT 3072
#define QSCALE 0.1803368801111f   // (1/8) * log2(e)

// smem BYTE offsets
#define B_KH   0            // K fp16 [64][72] halves = 9216B
#define B_VH   9216         // V fp16 [64][72] halves = 9216B
#define B_KSEG 18432        // 64 ints
#define B_CUS  18688        // 64 ints
#define SMEM_BYTES 18944

// split-K scratch (unnormalized O and l sums)
__device__ float OS[MAXT * HN * DD];
__device__ float LS[MAXT * HN];

__device__ __forceinline__ float ex2f(float x) {
    float y; asm("ex2.approx.ftz.f32 %0, %1;" : "=f"(y) : "f"(x)); return y;
}
__device__ __forceinline__ uint32_t packh2(float lo, float hi) {
    half2 h = __floats2half2_rn(lo, hi);
    return *(uint32_t*)&h;
}
__device__ __forceinline__ void mma16(float* c, const uint32_t* a, uint32_t b0, uint32_t b1) {
    asm volatile("mma.sync.aligned.m16n8k16.row.col.f32.f16.f16.f32 "
                 "{%0,%1,%2,%3}, {%4,%5,%6,%7}, {%8,%9}, {%0,%1,%2,%3};"
                 : "+f"(c[0]), "+f"(c[1]), "+f"(c[2]), "+f"(c[3])
                 : "r"(a[0]), "r"(a[1]), "r"(a[2]), "r"(a[3]), "r"(b0), "r"(b1));
}
__device__ __forceinline__ void ldsm4(uint32_t* r, uint32_t addr) {
    asm volatile("ldmatrix.sync.aligned.m8n8.x4.shared.b16 {%0,%1,%2,%3}, [%4];"
                 : "=r"(r[0]), "=r"(r[1]), "=r"(r[2]), "=r"(r[3]) : "r"(addr));
}
__device__ __forceinline__ void ldsm4t(uint32_t* r, uint32_t addr) {
    asm volatile("ldmatrix.sync.aligned.m8n8.x4.trans.shared.b16 {%0,%1,%2,%3}, [%4];"
                 : "=r"(r[0]), "=r"(r[1]), "=r"(r[2]), "=r"(r[3]) : "r"(addr));
}
__device__ __forceinline__ uint32_t s2u(const void* p) {
    uint32_t a;
    asm("{ .reg .u64 t; cvta.to.shared.u64 t, %1; cvt.u32.u64 %0, t; }" : "=r"(a) : "l"(p));
    return a;
}

__global__ void zero_scratch() {
    int i = blockIdx.x * 256 + threadIdx.x;
    float4 z = make_float4(0.f, 0.f, 0.f, 0.f);
    ((float4*)OS)[i] = z;                       // 786432 float4s, grid covers exactly
    if (i < MAXT * HN / 4) ((float4*)LS)[i] = z;
}

__global__ void norm_out(float* __restrict__ out) {
    int gid = blockIdx.x * 256 + threadIdx.x;   // one float4 each
    int row = gid >> 4;
    float l = LS[row];
    if (l == 0.f) return;                       // direct-path row: out already written
    float inv = 1.f / l;
    float4 v = ((const float4*)OS)[gid];
    v.x *= inv; v.y *= inv; v.z *= inv; v.w *= inv;
    ((float4*)out)[gid] = v;
}

__global__ __launch_bounds__(NT, 4) void varlen_attn_sk(
    const float* __restrict__ qg, const float* __restrict__ kg, const float* __restrict__ vg,
    const int* __restrict__ cuq, const int* __restrict__ cuk,
    float* __restrict__ out, int T, int ncu)
{
    extern __shared__ char smc[];
    const uint32_t sb = s2u(smc);
    int* kseg = (int*)(smc + B_KSEG);
    int* cus  = (int*)(smc + B_CUS);

    const int tid  = threadIdx.x;
    const int w    = tid >> 5;
    const int lane = tid & 31;
    const int g    = lane >> 2;
    const int tig  = lane & 3;
    const int h  = blockIdx.y;
    const int q0 = blockIdx.x * BQ;
    const int sp = blockIdx.z;

    const uint32_t lmoff = (uint32_t)(((lane & 7) + 8 * ((lane >> 3) & 1)) * 144 + (lane >> 4) * 16);
    const uint32_t klane = sb + B_KH + lmoff;
    const uint32_t vlane = sb + B_VH + lmoff;

    if (tid < ncu) cus[tid] = cuk[tid];
    __syncthreads();

    const int t0g = q0 + w * 16 + g;
    const int t1g = t0g + 8;
    int qs0 = 0, qs1 = 0, sfirst = 0, slast = 0;
    {
        const int tl = min(q0 + BQ - 1, T - 1);
        for (int i = 1; i < ncu - 1; i++) {
            int c = cus[i];
            qs0 += (c <= t0g); qs1 += (c <= t1g);
            sfirst += (c <= q0); slast += (c <= tl);
        }
    }
    const int kbeg = cus[sfirst];
    const int kend = cus[slast + 1];
    const int tile0 = kbeg >> 6;
    const int ntiles = ((kend - 1) >> 6) - tile0 + 1;
    const int nact = (ntiles + KCAP - 1) / KCAP;
    if (sp >= nact) return;                       // idle split: cheap exit
    const bool direct = (nact == 1);
    const int jbeg = sp * KCAP;
    const int jend = min(jbeg + KCAP, ntiles);

    // ---- Q fragments ----
    uint32_t qaf[4][4];
    {
        const float* qp0 = qg + (size_t)t0g * (HN * DD) + h * DD;
        const float* qp1 = qg + (size_t)t1g * (HN * DD) + h * DD;
        #pragma unroll
        for (int kk = 0; kk < 4; kk++) {
            int d0 = kk * 16 + 2 * tig;
            float2 a = *(const float2*)(qp0 + d0);
            float2 b = *(const float2*)(qp1 + d0);
            float2 c = *(const float2*)(qp0 + d0 + 8);
            float2 d = *(const float2*)(qp1 + d0 + 8);
            qaf[kk][0] = packh2(a.x * QSCALE, a.y * QSCALE);
            qaf[kk][1] = packh2(b.x * QSCALE, b.y * QSCALE);
            qaf[kk][2] = packh2(c.x * QSCALE, c.y * QSCALE);
            qaf[kk][3] = packh2(d.x * QSCALE, d.y * QSCALE);
        }
    }

    float oacc[8][4];
    #pragma unroll
    for (int n = 0; n < 8; n++)
        #pragma unroll
        for (int j = 0; j < 4; j++) oacc[n][j] = 0.f;
    float l0 = 0.f, l1 = 0.f;

    for (int j = jbeg; j < jend; j++) {
        const int kt = (tile0 + j) << 6;
        __syncthreads();

        // ---- load K,V tile: LDG fp32 -> cvt fp16 -> STS ----
        #pragma unroll
        for (int i = 0; i < 8; i++) {
            int idx = tid + i * NT;
            int r = idx >> 4, c4 = idx & 15;
            size_t gb = (size_t)(kt + r) * (HN * DD) + h * DD + c4 * 4;
            float4 kv = *(const float4*)(kg + gb);
            float4 vv = *(const float4*)(vg + gb);
            uint32_t so = (uint32_t)((r * 72 + c4 * 4) * 2);
            *(uint2*)(smc + B_KH + so) = make_uint2(packh2(kv.x, kv.y), packh2(kv.z, kv.w));
            *(uint2*)(smc + B_VH + so) = make_uint2(packh2(vv.x, vv.y), packh2(vv.z, vv.w));
        }
        if (tid < BK) {
            int t = kt + tid;
            int s = 0;
            for (int i = 1; i < ncu - 1; i++) s += (cus[i] <= t);
            kseg[tid] = s;
        }
        __syncthreads();

        // ---- S = Q K^T ----
        float sacc[8][4];
        #pragma unroll
        for (int n = 0; n < 8; n++)
            #pragma unroll
            for (int jj = 0; jj < 4; jj++) sacc[n][jj] = 0.f;

        #pragma unroll
        for (int kk = 0; kk < 4; kk++) {
            #pragma unroll
            for (int np = 0; np < 4; np++) {
                uint32_t kf[4];
                ldsm4(kf, klane + np * 2304 + kk * 32);
                mma16(sacc[2 * np],     qaf[kk], kf[0], kf[2]);
                mma16(sacc[2 * np + 1], qaf[kk], kf[1], kf[3]);
            }
        }

        // ---- mask + exp2 + pack ----
        uint32_t af[4][4];
        #pragma unroll
        for (int kk = 0; kk < 4; kk++) {
            #pragma unroll
            for (int hf = 0; hf < 2; hf++) {
                int jj = 2 * kk + hf;
                int kc = jj * 8 + 2 * tig;
                int2 ks2 = *(const int2*)&kseg[kc];
                float p00 = (ks2.x == qs0) ? ex2f(sacc[jj][0]) : 0.f;
                float p01 = (ks2.y == qs0) ? ex2f(sacc[jj][1]) : 0.f;
                float p10 = (ks2.x == qs1) ? ex2f(sacc[jj][2]) : 0.f;
                float p11 = (ks2.y == qs1) ? ex2f(sacc[jj][3]) : 0.f;
                l0 += p00 + p01;
                l1 += p10 + p11;
                af[kk][2 * hf + 0] = packh2(p00, p01);
                af[kk][2 * hf + 1] = packh2(p10, p11);
            }
        }

        // ---- O += P V ----
        #pragma unroll
        for (int kk = 0; kk < 4; kk++) {
            #pragma unroll
            for (int np = 0; np < 4; np++) {
                uint32_t vf[4];
                ldsm4t(vf, vlane + kk * 2304 + np * 32);
                mma16(oacc[2 * np],     af[kk], vf[0], vf[1]);
                mma16(oacc[2 * np + 1], af[kk], vf[2], vf[3]);
            }
        }
    }

    // ---- epilogue ----
    l0 += __shfl_xor_sync(0xffffffffu, l0, 1);
    l0 += __shfl_xor_sync(0xffffffffu, l0, 2);
    l1 += __shfl_xor_sync(0xffffffffu, l1, 1);
    l1 += __shfl_xor_sync(0xffffffffu, l1, 2);

    if (direct) {
        float i0 = 1.f / l0;
        float i1 = 1.f / l1;
        float* o0 = out + (size_t)t0g * (HN * DD) + h * DD;
        float* o1 = out + (size_t)t1g * (HN * DD) + h * DD;
        #pragma unroll
        for (int n = 0; n < 8; n++) {
            int c = n * 8 + 2 * tig;
            *(float2*)(o0 + c) = make_float2(oacc[n][0] * i0, oacc[n][1] * i0);
            *(float2*)(o1 + c) = make_float2(oacc[n][2] * i1, oacc[n][3] * i1);
        }
    } else {
        float* s0 = OS + (size_t)t0g * (HN * DD) + h * DD;
        float* s1 = OS + (size_t)t1g * (HN * DD) + h * DD;
        #pragma unroll
        for (int n = 0; n < 8; n++) {
            int c = n * 8 + 2 * tig;
            atomicAdd(s0 + c,     oacc[n][0]);
            atomicAdd(s0 + c + 1, oacc[n][1]);
            atomicAdd(s1 + c,     oacc[n][2]);
            atomicAdd(s1 + c + 1, oacc[n][3]);
        }
        if (tig == 0) {
            atomicAdd(&LS[t0g * HN + h], l0);
            atomicAdd(&LS[t1g * HN + h], l1);
        }
    }
}

extern "C" void kernel_launch(void* const* d_in, const int* in_sizes, int n_in,
                              void* d_out, int out_size)
{
    const float* q = (const float*)d_in[0];
    const float* k = (const float*)d_in[1];
    const float* v = (const float*)d_in[2];
    const int* cuq = (const int*)d_in[3];
    const int* cuk = (const int*)d_in[4];

    int T = in_sizes[0] / (HN * DD);
    int ncu = in_sizes[3];

    cudaFuncSetAttribute(varlen_attn_sk,
                         cudaFuncAttributeMaxDynamicSharedMemorySize, SMEM_BYTES);

    zero_scratch<<<(MAXT * HN * DD / 4) / 256, 256>>>();

    dim3 grid((T + BQ - 1) / BQ, HN, NSGRID);
    varlen_attn_sk<<<grid, NT, SMEM_BYTES>>>(q, k, v, cuq, cuk, (float*)d_out, T, ncu);

    norm_out<<<(T * HN * DD / 4) / 256, 256>>>((float*)d_out);
}

// round 9
// speedup vs baseline: 1.3660x; 1.3660x over previous
#include <cuda_runtime.h>
#include <cuda_fp16.h>
#include <cstdint>

#define HN 16
#define DD 64
#define BQ 64
#define BK 64
#define NT 128
#define MAXT 3072
#define QSCALE 0.1803368801111f   // (1/8) * log2(e)

// per-stage smem layout (bytes)
#define S_K   0          // K fp16 [64][64], swizzled 128B rows = 8192
#define S_V   8192       // V fp16 same = 8192
#define S_SEG 16384      // 64 ints = 256
#define STG_BYTES 16640
#define SMEM_BYTES (2 * STG_BYTES)

__device__ __half QH[MAXT * HN * DD];
__device__ __half KH[MAXT * HN * DD];
__device__ __half VH[MAXT * HN * DD];
__device__ int SEG[MAXT];

__device__ __forceinline__ float ex2f(float x) {
    float y; asm("ex2.approx.ftz.f32 %0, %1;" : "=f"(y) : "f"(x)); return y;
}
__device__ __forceinline__ uint32_t packh2(float lo, float hi) {
    half2 h = __floats2half2_rn(lo, hi);
    return *(uint32_t*)&h;
}
__device__ __forceinline__ void mma16(float* c, const uint32_t* a, uint32_t b0, uint32_t b1) {
    asm volatile("mma.sync.aligned.m16n8k16.row.col.f32.f16.f16.f32 "
                 "{%0,%1,%2,%3}, {%4,%5,%6,%7}, {%8,%9}, {%0,%1,%2,%3};"
                 : "+f"(c[0]), "+f"(c[1]), "+f"(c[2]), "+f"(c[3])
                 : "r"(a[0]), "r"(a[1]), "r"(a[2]), "r"(a[3]), "r"(b0), "r"(b1));
}
__device__ __forceinline__ void ldsm4(uint32_t* r, uint32_t addr) {
    asm volatile("ldmatrix.sync.aligned.m8n8.x4.shared.b16 {%0,%1,%2,%3}, [%4];"
                 : "=r"(r[0]), "=r"(r[1]), "=r"(r[2]), "=r"(r[3]) : "r"(addr));
}
__device__ __forceinline__ void ldsm4t(uint32_t* r, uint32_t addr) {
    asm volatile("ldmatrix.sync.aligned.m8n8.x4.trans.shared.b16 {%0,%1,%2,%3}, [%4];"
                 : "=r"(r[0]), "=r"(r[1]), "=r"(r[2]), "=r"(r[3]) : "r"(addr));
}
__device__ __forceinline__ uint32_t s2u(const void* p) {
    uint32_t a;
    asm("{ .reg .u64 t; cvta.to.shared.u64 t, %1; cvt.u32.u64 %0, t; }" : "=r"(a) : "l"(p));
    return a;
}
__device__ __forceinline__ void cpasync16(uint32_t saddr, const void* gaddr) {
    asm volatile("cp.async.cg.shared.global [%0], [%1], 16;" :: "r"(saddr), "l"(gaddr));
}
#define CP_COMMIT() asm volatile("cp.async.commit_group;" ::: "memory")
#define CP_WAIT0()  asm volatile("cp.async.wait_group 0;" ::: "memory")

// ---- prep: fp32 [t][h][d] -> fp16 [h][t][d] (Q pre-scaled), SEG[t] ----
__global__ void prep(const float* __restrict__ q, const float* __restrict__ k,
                     const float* __restrict__ v, const int* __restrict__ cu,
                     int T, int ncu)
{
    int gid = blockIdx.x * 256 + threadIdx.x;     // T*HN*16 threads
    int t = gid >> 8, rem = gid & 255;
    int h = rem >> 4, d4 = rem & 15;
    size_t src = (size_t)t * (HN * DD) + h * DD + d4 * 4;
    size_t dst = ((size_t)h * T + t) * DD + d4 * 4;
    float4 qv = *(const float4*)(q + src);
    float4 kv = *(const float4*)(k + src);
    float4 vv = *(const float4*)(v + src);
    *(uint2*)(QH + dst) = make_uint2(packh2(qv.x * QSCALE, qv.y * QSCALE),
                                     packh2(qv.z * QSCALE, qv.w * QSCALE));
    *(uint2*)(KH + dst) = make_uint2(packh2(kv.x, kv.y), packh2(kv.z, kv.w));
    *(uint2*)(VH + dst) = make_uint2(packh2(vv.x, vv.y), packh2(vv.z, vv.w));
    if (gid < T) {
        int s = 0;
        for (int i = 1; i < ncu - 1; i++) s += (cu[i] <= gid);
        SEG[gid] = s;
    }
}

__global__ __launch_bounds__(NT, 4) void varlen_attn_h4(
    const int* __restrict__ cuk, float* __restrict__ out, int T, int ncu)
{
    extern __shared__ char smc[];
    const uint32_t sb = s2u(smc);

    const int tid  = threadIdx.x;
    const int w    = tid >> 5;
    const int lane = tid & 31;
    const int g    = lane >> 2;
    const int tig  = lane & 3;
    const int h  = blockIdx.y;
    const int q0 = blockIdx.x * BQ;

    // ldmatrix lane constants
    const int r0    = (lane & 7) + 8 * ((lane >> 3) & 1);
    const int cbase = lane >> 4;
    const int xorv  = lane & 7;

    const int t0g = q0 + w * 16 + g;
    const int t1g = t0g + 8;
    const int qs0 = SEG[t0g];
    const int qs1 = SEG[t1g];
    const int sfirst = SEG[q0];
    const int slast  = SEG[min(q0 + BQ - 1, T - 1)];
    const int kbeg = cuk[sfirst];
    const int kend = cuk[slast + 1];
    const int kt0 = (kbeg >> 6) << 6;
    const int ntl = ((kend - 1) >> 6) - (kbeg >> 6) + 1;

    const __half* kh = KH + (size_t)h * T * DD;
    const __half* vh = VH + (size_t)h * T * DD;

    // ---- issue tile 0 into stage 0 ----
    {
        #pragma unroll
        for (int i = 0; i < 4; i++) {
            int idx = tid + i * NT;          // 0..511
            int r = idx >> 3, c = idx & 7;
            uint32_t so = (uint32_t)(r * 128 + ((c ^ (r & 7)) << 4));
            const __half* src = kh + (size_t)(kt0 + r) * DD + c * 8;
            cpasync16(sb + S_K + so, src);
            cpasync16(sb + S_V + so, vh + (size_t)(kt0 + r) * DD + c * 8);
        }
        if (tid < 16) cpasync16(sb + S_SEG + tid * 16, SEG + kt0 + tid * 4);
        CP_COMMIT();
    }

    // ---- Q fragments from pre-scaled fp16 ----
    uint32_t qaf[4][4];
    {
        const __half* qp0 = QH + ((size_t)h * T + t0g) * DD;
        const __half* qp1 = QH + ((size_t)h * T + t1g) * DD;
        #pragma unroll
        for (int kk = 0; kk < 4; kk++) {
            int d0 = kk * 16 + 2 * tig;
            qaf[kk][0] = *(const uint32_t*)(qp0 + d0);
            qaf[kk][1] = *(const uint32_t*)(qp1 + d0);
            qaf[kk][2] = *(const uint32_t*)(qp0 + d0 + 8);
            qaf[kk][3] = *(const uint32_t*)(qp1 + d0 + 8);
        }
    }

    float oacc[8][4];
    #pragma unroll
    for (int n = 0; n < 8; n++)
        #pragma unroll
        for (int j = 0; j < 4; j++) oacc[n][j] = 0.f;
    float l0 = 0.f, l1 = 0.f;

    for (int it = 0; it < ntl; it++) {
        const uint32_t stg = sb + (it & 1) * STG_BYTES;

        CP_WAIT0();
        __syncthreads();    // tile ready for all; all threads past previous compute

        // ---- issue next tile into alternate stage (overlaps compute) ----
        if (it + 1 < ntl) {
            const int ktn = kt0 + (it + 1) * BK;
            const uint32_t st2 = sb + ((it + 1) & 1) * STG_BYTES;
            #pragma unroll
            for (int i = 0; i < 4; i++) {
                int idx = tid + i * NT;
                int r = idx >> 3, c = idx & 7;
                uint32_t so = (uint32_t)(r * 128 + ((c ^ (r & 7)) << 4));
                cpasync16(st2 + S_K + so, kh + (size_t)(ktn + r) * DD + c * 8);
                cpasync16(st2 + S_V + so, vh + (size_t)(ktn + r) * DD + c * 8);
            }
            if (tid < 16) cpasync16(st2 + S_SEG + tid * 16, SEG + ktn + tid * 4);
        }
        CP_COMMIT();

        // ---- S = Q K^T ----
        float sacc[8][4];
        #pragma unroll
        for (int n = 0; n < 8; n++)
            #pragma unroll
            for (int jj = 0; jj < 4; jj++) sacc[n][jj] = 0.f;

        #pragma unroll
        for (int kk = 0; kk < 4; kk++) {
            #pragma unroll
            for (int np = 0; np < 4; np++) {
                uint32_t kf[4];
                uint32_t addr = stg + S_K + (uint32_t)((r0 + np * 16) * 128 +
                                (((2 * kk + cbase) ^ xorv) << 4));
                ldsm4(kf, addr);
                mma16(sacc[2 * np],     qaf[kk], kf[0], kf[2]);
                mma16(sacc[2 * np + 1], qaf[kk], kf[1], kf[3]);
            }
        }

        // ---- mask + exp2 + pack to A-fragments ----
        uint32_t af[4][4];
        #pragma unroll
        for (int kk = 0; kk < 4; kk++) {
            #pragma unroll
            for (int hf = 0; hf < 2; hf++) {
                int jj = 2 * kk + hf;
                int kc = jj * 8 + 2 * tig;
                int2 ks2 = *(const int2*)(smc + (stg - sb) + S_SEG + kc * 4);
                float p00 = (ks2.x == qs0) ? ex2f(sacc[jj][0]) : 0.f;
                float p01 = (ks2.y == qs0) ? ex2f(sacc[jj][1]) : 0.f;
                float p10 = (ks2.x == qs1) ? ex2f(sacc[jj][2]) : 0.f;
                float p11 = (ks2.y == qs1) ? ex2f(sacc[jj][3]) : 0.f;
                l0 += p00 + p01;
                l1 += p10 + p11;
                af[kk][2 * hf + 0] = packh2(p00, p01);
                af[kk][2 * hf + 1] = packh2(p10, p11);
            }
        }

        // ---- O += P V ----
        #pragma unroll
        for (int kk = 0; kk < 4; kk++) {
            #pragma unroll
            for (int np = 0; np < 4; np++) {
                uint32_t vf[4];
                uint32_t addr = stg + S_V + (uint32_t)((r0 + kk * 16) * 128 +
                                (((2 * np + cbase) ^ xorv) << 4));
                ldsm4t(vf, addr);
                mma16(oacc[2 * np],     af[kk], vf[0], vf[1]);
                mma16(oacc[2 * np + 1], af[kk], vf[2], vf[3]);
            }
        }
    }

    // ---- epilogue ----
    l0 += __shfl_xor_sync(0xffffffffu, l0, 1);
    l0 += __shfl_xor_sync(0xffffffffu, l0, 2);
    l1 += __shfl_xor_sync(0xffffffffu, l1, 1);
    l1 += __shfl_xor_sync(0xffffffffu, l1, 2);
    float i0 = 1.f / l0;
    float i1 = 1.f / l1;

    float* o0 = out + (size_t)t0g * (HN * DD) + h * DD;
    float* o1 = out + (size_t)t1g * (HN * DD) + h * DD;
    #pragma unroll
    for (int n = 0; n < 8; n++) {
        int c = n * 8 + 2 * tig;
        *(float2*)(o0 + c) = make_float2(oacc[n][0] * i0, oacc[n][1] * i0);
        *(float2*)(o1 + c) = make_float2(oacc[n][2] * i1, oacc[n][3] * i1);
    }
}

extern "C" void kernel_launch(void* const* d_in, const int* in_sizes, int n_in,
                              void* d_out, int out_size)
{
    const float* q = (const float*)d_in[0];
    const float* k = (const float*)d_in[1];
    const float* v = (const float*)d_in[2];
    const int* cuk = (const int*)d_in[4];

    int T = in_sizes[0] / (HN * DD);
    int ncu = in_sizes[3];

    cudaFuncSetAttribute(varlen_attn_h4,
                         cudaFuncAttributeMaxDynamicSharedMemorySize, SMEM_BYTES);

    prep<<<(T * HN * 16) / 256, 256>>>(q, k, v, cuk, T, ncu);

    dim3 grid((T + BQ - 1) / BQ, HN);
    varlen_attn_h4<<<grid, NT, SMEM_BYTES>>>(cuk, (float*)d_out, T, ncu);
}